// round 3
// baseline (speedup 1.0000x reference)
#include <cuda_runtime.h>
#include <math.h>

#define S_LEN   8192
#define BATCH   4
#define DMODEL  1024
#define NROWS   (BATCH * S_LEN)   // 32768
#define NHEADS  16
#define DHEAD   64

// Scratch (device globals: allocation-free per harness rules)
__device__ float g_q[(size_t)NROWS * DMODEL];
__device__ float g_k[(size_t)NROWS * DMODEL];
__device__ float g_v[(size_t)NROWS * DMODEL];
__device__ float g_attn[(size_t)NROWS * DMODEL];
__device__ float g_kv[BATCH * NHEADS * DHEAD * DHEAD];   // [b,h,dv,dk]
__device__ float g_ksum[BATCH * NHEADS * DHEAD];

// ---------------------------------------------------------------------------
// tf32 helpers
// ---------------------------------------------------------------------------
__device__ __forceinline__ unsigned f2tf(float f) {
    unsigned u;
    asm("cvt.rna.tf32.f32 %0, %1;" : "=r"(u) : "f"(f));
    return u;
}

__device__ __forceinline__ void mma_tf32(float* c, const unsigned* a, const unsigned* b) {
    asm volatile(
        "mma.sync.aligned.m16n8k8.row.col.f32.tf32.tf32.f32 "
        "{%0,%1,%2,%3}, {%4,%5,%6,%7}, {%8,%9}, {%0,%1,%2,%3};"
        : "+f"(c[0]), "+f"(c[1]), "+f"(c[2]), "+f"(c[3])
        : "r"(a[0]), "r"(a[1]), "r"(a[2]), "r"(a[3]), "r"(b[0]), "r"(b[1]));
}

// ---------------------------------------------------------------------------
// Zero kernel (for atomic accumulators)
// ---------------------------------------------------------------------------
__global__ void zero_kernel(float* p, int n) {
    int i = blockIdx.x * blockDim.x + threadIdx.x;
    if (i < n) p[i] = 0.0f;
}

// ---------------------------------------------------------------------------
// GEMM: C[M,1024] = A[M,1024] @ W[1024,1024]^T + bias, optional elu+1 epilogue
//
// tf32 converted ONCE at the smem-store stage (STS.128, identity layout).
// Inner loop uses the k-reassignment trick: thread tg carries k = {2tg, 2tg+1}
// (instead of {tg, tg+4}) for BOTH operands -> every fragment load is a
// contiguous, conflict-free LDS.64 (SPAD=40: addr64 = 20g+tg distinct mod 16).
// Single static smem buffer, 2 CTAs/SM pinned via launch_bounds.
// BM=128, BN=128, BK=32, 256 threads, 8 warps (2x4), warp tile 64x32
// ---------------------------------------------------------------------------
#define BM 128
#define BN 128
#define BK 32
#define SPAD 40

template <int EPI>
__global__ void __launch_bounds__(256, 2)
gemm_tf32_kernel(const float* __restrict__ A, const float* __restrict__ W,
                 const float* __restrict__ bias, float* __restrict__ C) {
    __shared__ unsigned As[BM * SPAD];
    __shared__ unsigned Bs[BN * SPAD];

    const int tid  = threadIdx.x;
    const int lane = tid & 31;
    const int warp = tid >> 5;
    const int wm   = (warp & 1) * 64;   // warp row offset in tile
    const int wn   = (warp >> 1) * 32;  // warp col offset in tile
    const int m0   = blockIdx.y * BM;
    const int n0   = blockIdx.x * BN;
    const int g    = lane >> 2;         // groupID 0..7
    const int tg   = lane & 3;          // thread-in-group 0..3

    // global-load mapping: each thread loads 4 float4 per operand per k-tile
    const int lr  = tid >> 3;           // row base (0..31), + 32*i
    const int lc4 = (tid & 7) << 2;     // col base within BK (0,4,..,28)

    float acc[4][4][4];
#pragma unroll
    for (int mt = 0; mt < 4; mt++)
#pragma unroll
        for (int nt = 0; nt < 4; nt++)
#pragma unroll
            for (int i = 0; i < 4; i++) acc[mt][nt][i] = 0.0f;

    for (int k0 = 0; k0 < DMODEL; k0 += BK) {
        __syncthreads();
        // load + convert + store (vector STS.128, conflict-free)
#pragma unroll
        for (int i = 0; i < 4; i++) {
            int r = lr + 32 * i;
            float4 va = *(const float4*)&A[(size_t)(m0 + r) * DMODEL + k0 + lc4];
            float4 vb = *(const float4*)&W[(size_t)(n0 + r) * DMODEL + k0 + lc4];
            uint4 ua = make_uint4(f2tf(va.x), f2tf(va.y), f2tf(va.z), f2tf(va.w));
            uint4 ub = make_uint4(f2tf(vb.x), f2tf(vb.y), f2tf(vb.z), f2tf(vb.w));
            *(uint4*)&As[r * SPAD + lc4] = ua;
            *(uint4*)&Bs[r * SPAD + lc4] = ub;
        }
        __syncthreads();

#pragma unroll
        for (int ks = 0; ks < 4; ks++) {
            const int kk = ks * 8 + 2 * tg;   // this thread's k pair base
            unsigned a[4][4], b[4][2];
#pragma unroll
            for (int mt = 0; mt < 4; mt++) {
                int base = (wm + mt * 16 + g) * SPAD + kk;
                uint2 lo = *(const uint2*)&As[base];
                uint2 hi = *(const uint2*)&As[base + 8 * SPAD];
                a[mt][0] = lo.x; a[mt][1] = hi.x; a[mt][2] = lo.y; a[mt][3] = hi.y;
            }
#pragma unroll
            for (int nt = 0; nt < 4; nt++) {
                uint2 bb = *(const uint2*)&Bs[(wn + nt * 8 + g) * SPAD + kk];
                b[nt][0] = bb.x; b[nt][1] = bb.y;
            }
#pragma unroll
            for (int mt = 0; mt < 4; mt++)
#pragma unroll
                for (int nt = 0; nt < 4; nt++)
                    mma_tf32(acc[mt][nt], a[mt], b[nt]);
        }
    }

    // epilogue: bias + optional elu(x)+1 feature map, float2 stores
#pragma unroll
    for (int mt = 0; mt < 4; mt++) {
#pragma unroll
        for (int nt = 0; nt < 4; nt++) {
            int row = m0 + wm + mt * 16 + g;
            int col = n0 + wn + nt * 8 + 2 * tg;
            float bv0 = bias[col];
            float bv1 = bias[col + 1];
            float v00 = acc[mt][nt][0] + bv0;
            float v01 = acc[mt][nt][1] + bv1;
            float v10 = acc[mt][nt][2] + bv0;
            float v11 = acc[mt][nt][3] + bv1;
            if (EPI) {
                v00 = (v00 > 0.0f) ? v00 + 1.0f : expf(v00);
                v01 = (v01 > 0.0f) ? v01 + 1.0f : expf(v01);
                v10 = (v10 > 0.0f) ? v10 + 1.0f : expf(v10);
                v11 = (v11 > 0.0f) ? v11 + 1.0f : expf(v11);
            }
            float2 o0 = make_float2(v00, v01);
            float2 o1 = make_float2(v10, v11);
            *(float2*)&C[(size_t)row * DMODEL + col]       = o0;
            *(float2*)&C[(size_t)(row + 8) * DMODEL + col] = o1;
        }
    }
}

// ---------------------------------------------------------------------------
// KV chain: kv[b,h,i,j] = sum_s V[b,s,h,i] * K[b,s,h,j];  ksum[b,h,j] = sum_s K
// grid (64 bh, 8 s-chunks of 1024), 256 threads (16x16), each thread 4x4 outer product
// ---------------------------------------------------------------------------
__global__ void __launch_bounds__(256)
kv_kernel(const float* __restrict__ K, const float* __restrict__ V,
          float* __restrict__ kv, float* __restrict__ ksum) {
    const int bh = blockIdx.x;              // b*NHEADS + h
    const int b  = bh / NHEADS;
    const int h  = bh % NHEADS;
    const int tid = threadIdx.x;
    const int ty  = tid >> 4;
    const int tx  = tid & 15;

    __shared__ float Ks[16][64];
    __shared__ float Vs[16][64];

    float acc[4][4];
#pragma unroll
    for (int i = 0; i < 4; i++)
#pragma unroll
        for (int j = 0; j < 4; j++) acc[i][j] = 0.0f;
    float ks_acc = 0.0f;

    const float* Kbase = K + (size_t)b * S_LEN * DMODEL + h * DHEAD;
    const float* Vbase = V + (size_t)b * S_LEN * DMODEL + h * DHEAD;
    const int s0 = blockIdx.y * (S_LEN / 8);

    for (int s = s0; s < s0 + (S_LEN / 8); s += 16) {
        __syncthreads();
        {
            int r  = tid >> 4;
            int c4 = (tid & 15) << 2;
            *(float4*)&Ks[r][c4] = *(const float4*)&Kbase[(size_t)(s + r) * DMODEL + c4];
            *(float4*)&Vs[r][c4] = *(const float4*)&Vbase[(size_t)(s + r) * DMODEL + c4];
        }
        __syncthreads();
        if (tid < 64) {
#pragma unroll
            for (int ss = 0; ss < 16; ss++) ks_acc += Ks[ss][tid];
        }
#pragma unroll
        for (int ss = 0; ss < 16; ss++) {
            float vr[4], kr[4];
#pragma unroll
            for (int i = 0; i < 4; i++) vr[i] = Vs[ss][ty * 4 + i];
#pragma unroll
            for (int j = 0; j < 4; j++) kr[j] = Ks[ss][tx * 4 + j];
#pragma unroll
            for (int i = 0; i < 4; i++)
#pragma unroll
                for (int j = 0; j < 4; j++) acc[i][j] += vr[i] * kr[j];
        }
    }

    float* kvbh = kv + (size_t)bh * DHEAD * DHEAD;
#pragma unroll
    for (int i = 0; i < 4; i++)
#pragma unroll
        for (int j = 0; j < 4; j++)
            atomicAdd(&kvbh[(ty * 4 + i) * DHEAD + tx * 4 + j], acc[i][j]);
    if (tid < 64) atomicAdd(&ksum[bh * DHEAD + tid], ks_acc);
}

// ---------------------------------------------------------------------------
// Attention apply: attn[t, h*64+i] = norm * sum_d q[t,h,d] * kv[b,h,i,d]
// norm = 1/(sum_d q[t,h,d]*ksum[b,h,d] + eps)
// grid (NROWS/128, NHEADS), 128 threads, one row per thread
// ---------------------------------------------------------------------------
__global__ void __launch_bounds__(128)
attn_kernel(const float* __restrict__ Q, const float* __restrict__ kv,
            const float* __restrict__ ksum, float* __restrict__ attn) {
    const int h   = blockIdx.y;
    const int row = blockIdx.x * 128 + threadIdx.x;
    const int b   = row / S_LEN;

    __shared__ float kvs[64][64];
    __shared__ float kss[64];

    const float* kvsrc = kv + (size_t)(b * NHEADS + h) * DHEAD * DHEAD;
    for (int i = threadIdx.x; i < (DHEAD * DHEAD) / 4; i += 128)
        ((float4*)kvs)[i] = ((const float4*)kvsrc)[i];
    if (threadIdx.x < 64) kss[threadIdx.x] = ksum[(b * NHEADS + h) * DHEAD + threadIdx.x];
    __syncthreads();

    float q[64];
    const float* qp = Q + (size_t)row * DMODEL + h * DHEAD;
#pragma unroll
    for (int i = 0; i < 16; i++) ((float4*)q)[i] = ((const float4*)qp)[i];

    float nd = 0.0f;
#pragma unroll
    for (int d = 0; d < 64; d++) nd += q[d] * kss[d];
    const float norm = 1.0f / (nd + 1e-6f);

    float* op = attn + (size_t)row * DMODEL + h * DHEAD;
    for (int i0 = 0; i0 < 64; i0 += 4) {
        float out[4];
#pragma unroll
        for (int u = 0; u < 4; u++) {
            float s = 0.0f;
            const float4* kv4 = (const float4*)kvs[i0 + u];
#pragma unroll
            for (int d4 = 0; d4 < 16; d4++) {
                float4 kvv = kv4[d4];
                s += q[4*d4] * kvv.x + q[4*d4+1] * kvv.y
                   + q[4*d4+2] * kvv.z + q[4*d4+3] * kvv.w;
            }
            out[u] = s * norm;
        }
        *(float4*)&op[i0] = make_float4(out[0], out[1], out[2], out[3]);
    }
}

// ---------------------------------------------------------------------------
// Launch
// ---------------------------------------------------------------------------
extern "C" void kernel_launch(void* const* d_in, const int* in_sizes, int n_in,
                              void* d_out, int out_size) {
    const float* query = (const float*)d_in[0];
    const float* key_  = (const float*)d_in[1];
    const float* value = (const float*)d_in[2];
    const float* Wq = (const float*)d_in[3];
    const float* bq = (const float*)d_in[4];
    const float* Wk = (const float*)d_in[5];
    const float* bk = (const float*)d_in[6];
    const float* Wv = (const float*)d_in[7];
    const float* bv = (const float*)d_in[8];
    const float* Wo = (const float*)d_in[9];
    const float* bo = (const float*)d_in[10];
    float* out = (float*)d_out;

    float *qf, *kf, *vf, *attn, *kv, *ks;
    cudaGetSymbolAddress((void**)&qf,   g_q);
    cudaGetSymbolAddress((void**)&kf,   g_k);
    cudaGetSymbolAddress((void**)&vf,   g_v);
    cudaGetSymbolAddress((void**)&attn, g_attn);
    cudaGetSymbolAddress((void**)&kv,   g_kv);
    cudaGetSymbolAddress((void**)&ks,   g_ksum);

    // zero accumulators for atomics
    zero_kernel<<<(BATCH * NHEADS * DHEAD * DHEAD + 255) / 256, 256>>>(kv, BATCH * NHEADS * DHEAD * DHEAD);
    zero_kernel<<<(BATCH * NHEADS * DHEAD + 255) / 256, 256>>>(ks, BATCH * NHEADS * DHEAD);

    dim3 gemm_grid(DMODEL / BN, NROWS / BM);  // (8, 256)
    gemm_tf32_kernel<1><<<gemm_grid, 256>>>(query, Wq, bq, qf);
    gemm_tf32_kernel<1><<<gemm_grid, 256>>>(key_,  Wk, bk, kf);
    gemm_tf32_kernel<0><<<gemm_grid, 256>>>(value, Wv, bv, vf);

    kv_kernel<<<dim3(BATCH * NHEADS, 8), 256>>>(kf, vf, kv, ks);

    attn_kernel<<<dim3(NROWS / 128, NHEADS), 128>>>(qf, kv, ks, attn);

    gemm_tf32_kernel<0><<<gemm_grid, 256>>>(attn, Wo, bo, out);
}

// round 4
// speedup vs baseline: 1.6669x; 1.6669x over previous
#include <cuda_runtime.h>
#include <math.h>

#define S_LEN   8192
#define BATCH   4
#define DMODEL  1024
#define NROWS   (BATCH * S_LEN)   // 32768
#define NHEADS  16
#define DHEAD   64

// Scratch (device globals: allocation-free per harness rules)
__device__ float g_q[(size_t)NROWS * DMODEL];
__device__ float g_k[(size_t)NROWS * DMODEL];
__device__ float g_v[(size_t)NROWS * DMODEL];
__device__ float g_attn[(size_t)NROWS * DMODEL];
__device__ float g_rq[(size_t)NROWS * DMODEL];   // tf32-rounded inputs
__device__ float g_rk[(size_t)NROWS * DMODEL];
__device__ float g_rv[(size_t)NROWS * DMODEL];
__device__ float g_rw[4][DMODEL * DMODEL];       // tf32-rounded weights
__device__ float g_kv[BATCH * NHEADS * DHEAD * DHEAD];   // [b,h,dv,dk]
__device__ float g_ksum[BATCH * NHEADS * DHEAD];

// ---------------------------------------------------------------------------
// tf32 helpers
// ---------------------------------------------------------------------------
__device__ __forceinline__ unsigned f2tf(float f) {
    unsigned u;
    asm("cvt.rna.tf32.f32 %0, %1;" : "=r"(u) : "f"(f));
    return u;
}

__device__ __forceinline__ void mma_tf32(float* c, const unsigned* a, const unsigned* b) {
    asm volatile(
        "mma.sync.aligned.m16n8k8.row.col.f32.tf32.tf32.f32 "
        "{%0,%1,%2,%3}, {%4,%5,%6,%7}, {%8,%9}, {%0,%1,%2,%3};"
        : "+f"(c[0]), "+f"(c[1]), "+f"(c[2]), "+f"(c[3])
        : "r"(a[0]), "r"(a[1]), "r"(a[2]), "r"(a[3]), "r"(b[0]), "r"(b[1]));
}

__device__ __forceinline__ void cp_async16(unsigned smem_addr, const void* gptr) {
    asm volatile("cp.async.cg.shared.global [%0], [%1], 16;"
                 :: "r"(smem_addr), "l"(gptr));
}
__device__ __forceinline__ void cp_commit() {
    asm volatile("cp.async.commit_group;");
}
template <int N>
__device__ __forceinline__ void cp_wait() {
    asm volatile("cp.async.wait_group %0;" :: "n"(N));
}

// ---------------------------------------------------------------------------
// Elementwise tf32 rounding pass (stored as fp32 bit patterns)
// ---------------------------------------------------------------------------
__global__ void round_tf32_kernel(const float* __restrict__ in,
                                  float* __restrict__ out, int n4) {
    int i = blockIdx.x * blockDim.x + threadIdx.x;
    if (i < n4) {
        float4 v = ((const float4*)in)[i];
        uint4 u = make_uint4(f2tf(v.x), f2tf(v.y), f2tf(v.z), f2tf(v.w));
        ((uint4*)out)[i] = u;
    }
}

// ---------------------------------------------------------------------------
// Zero kernel (for atomic accumulators)
// ---------------------------------------------------------------------------
__global__ void zero_kernel(float* p, int n) {
    int i = blockIdx.x * blockDim.x + threadIdx.x;
    if (i < n) p[i] = 0.0f;
}

// ---------------------------------------------------------------------------
// GEMM: C[M,1024] = A[M,1024] @ W[1024,1024]^T + bias, optional elu+1 epilogue
// A and W are PRE-ROUNDED to tf32 -> no cvt anywhere in this kernel.
// cp.async double-buffered pipeline; conflict-free LDS.64 fragment loads via
// k-reassignment (thread tg carries k={2tg,2tg+1} for both operands).
// BM=128, BN=128, BK=32, 256 threads, 8 warps (2x4), warp tile 64x32
// ---------------------------------------------------------------------------
#define BM 128
#define BN 128
#define BK 32
#define SPAD 40
#define TILE_WORDS (BM * SPAD)
#define GEMM_SMEM_BYTES (4 * TILE_WORDS * 4)   // 2 bufs x (A + B) x 20KB

template <int EPI>
__global__ void __launch_bounds__(256)
gemm_tf32_kernel(const float* __restrict__ A, const float* __restrict__ W,
                 const float* __restrict__ bias, float* __restrict__ C) {
    extern __shared__ unsigned sh[];
    unsigned* Asm = sh;                       // [2][TILE_WORDS]
    unsigned* Bsm = sh + 2 * TILE_WORDS;      // [2][TILE_WORDS]

    const int tid  = threadIdx.x;
    const int lane = tid & 31;
    const int warp = tid >> 5;
    const int wm   = (warp & 1) * 64;
    const int wn   = (warp >> 1) * 32;
    const int m0   = blockIdx.y * BM;
    const int n0   = blockIdx.x * BN;
    const int g    = lane >> 2;
    const int tg   = lane & 3;

    const int lr  = tid >> 3;           // row base (0..31), + 32*i
    const int lc4 = (tid & 7) << 2;     // col base within BK

    // byte addresses in shared for cp.async destinations
    unsigned sbase = (unsigned)__cvta_generic_to_shared(sh);
    const unsigned a_dst0 = sbase + (lr * SPAD + lc4) * 4;
    const unsigned b_dst0 = a_dst0 + 2 * TILE_WORDS * 4;

    float acc[4][4][4];
#pragma unroll
    for (int mt = 0; mt < 4; mt++)
#pragma unroll
        for (int nt = 0; nt < 4; nt++)
#pragma unroll
            for (int i = 0; i < 4; i++) acc[mt][nt][i] = 0.0f;

    const float* Ap = &A[(size_t)(m0 + lr) * DMODEL + lc4];
    const float* Wp = &W[(size_t)(n0 + lr) * DMODEL + lc4];

    // prologue: stage 0
#pragma unroll
    for (int i = 0; i < 4; i++) {
        cp_async16(a_dst0 + i * 32 * SPAD * 4, Ap + (size_t)32 * i * DMODEL);
        cp_async16(b_dst0 + i * 32 * SPAD * 4, Wp + (size_t)32 * i * DMODEL);
    }
    cp_commit();

    const int NK = DMODEL / BK;   // 32
    for (int kt = 0; kt < NK; kt++) {
        const int buf = kt & 1;
        const unsigned nbuf_off = ((kt + 1) & 1) * TILE_WORDS * 4;
        // issue next stage
        if (kt + 1 < NK) {
            const float* Apn = Ap + (kt + 1) * BK;
            const float* Wpn = Wp + (kt + 1) * BK;
#pragma unroll
            for (int i = 0; i < 4; i++) {
                cp_async16(a_dst0 + nbuf_off + i * 32 * SPAD * 4, Apn + (size_t)32 * i * DMODEL);
                cp_async16(b_dst0 + nbuf_off + i * 32 * SPAD * 4, Wpn + (size_t)32 * i * DMODEL);
            }
            cp_commit();
            cp_wait<1>();
        } else {
            cp_wait<0>();
        }
        __syncthreads();

        const unsigned* Ab = Asm + buf * TILE_WORDS;
        const unsigned* Bb = Bsm + buf * TILE_WORDS;
#pragma unroll
        for (int ks = 0; ks < 4; ks++) {
            const int kk = ks * 8 + 2 * tg;
            unsigned a[4][4], b[4][2];
#pragma unroll
            for (int mt = 0; mt < 4; mt++) {
                int base = (wm + mt * 16 + g) * SPAD + kk;
                uint2 lo = *(const uint2*)&Ab[base];
                uint2 hi = *(const uint2*)&Ab[base + 8 * SPAD];
                a[mt][0] = lo.x; a[mt][1] = hi.x; a[mt][2] = lo.y; a[mt][3] = hi.y;
            }
#pragma unroll
            for (int nt = 0; nt < 4; nt++) {
                uint2 bb = *(const uint2*)&Bb[(wn + nt * 8 + g) * SPAD + kk];
                b[nt][0] = bb.x; b[nt][1] = bb.y;
            }
#pragma unroll
            for (int mt = 0; mt < 4; mt++)
#pragma unroll
                for (int nt = 0; nt < 4; nt++)
                    mma_tf32(acc[mt][nt], a[mt], b[nt]);
        }
        __syncthreads();   // protect buffer reuse before next issue
    }

    // epilogue: bias + optional elu(x)+1 feature map, float2 stores
#pragma unroll
    for (int mt = 0; mt < 4; mt++) {
#pragma unroll
        for (int nt = 0; nt < 4; nt++) {
            int row = m0 + wm + mt * 16 + g;
            int col = n0 + wn + nt * 8 + 2 * tg;
            float bv0 = bias[col];
            float bv1 = bias[col + 1];
            float v00 = acc[mt][nt][0] + bv0;
            float v01 = acc[mt][nt][1] + bv1;
            float v10 = acc[mt][nt][2] + bv0;
            float v11 = acc[mt][nt][3] + bv1;
            if (EPI) {
                v00 = (v00 > 0.0f) ? v00 + 1.0f : expf(v00);
                v01 = (v01 > 0.0f) ? v01 + 1.0f : expf(v01);
                v10 = (v10 > 0.0f) ? v10 + 1.0f : expf(v10);
                v11 = (v11 > 0.0f) ? v11 + 1.0f : expf(v11);
            }
            float2 o0 = make_float2(v00, v01);
            float2 o1 = make_float2(v10, v11);
            *(float2*)&C[(size_t)row * DMODEL + col]       = o0;
            *(float2*)&C[(size_t)(row + 8) * DMODEL + col] = o1;
        }
    }
}

// ---------------------------------------------------------------------------
// KV chain: kv[b,h,i,j] = sum_s V[b,s,h,i] * K[b,s,h,j];  ksum[b,h,j] = sum_s K
// ---------------------------------------------------------------------------
__global__ void __launch_bounds__(256)
kv_kernel(const float* __restrict__ K, const float* __restrict__ V,
          float* __restrict__ kv, float* __restrict__ ksum) {
    const int bh = blockIdx.x;
    const int b  = bh / NHEADS;
    const int h  = bh % NHEADS;
    const int tid = threadIdx.x;
    const int ty  = tid >> 4;
    const int tx  = tid & 15;

    __shared__ float Ks[16][64];
    __shared__ float Vs[16][64];

    float acc[4][4];
#pragma unroll
    for (int i = 0; i < 4; i++)
#pragma unroll
        for (int j = 0; j < 4; j++) acc[i][j] = 0.0f;
    float ks_acc = 0.0f;

    const float* Kbase = K + (size_t)b * S_LEN * DMODEL + h * DHEAD;
    const float* Vbase = V + (size_t)b * S_LEN * DMODEL + h * DHEAD;
    const int s0 = blockIdx.y * (S_LEN / 8);

    for (int s = s0; s < s0 + (S_LEN / 8); s += 16) {
        __syncthreads();
        {
            int r  = tid >> 4;
            int c4 = (tid & 15) << 2;
            *(float4*)&Ks[r][c4] = *(const float4*)&Kbase[(size_t)(s + r) * DMODEL + c4];
            *(float4*)&Vs[r][c4] = *(const float4*)&Vbase[(size_t)(s + r) * DMODEL + c4];
        }
        __syncthreads();
        if (tid < 64) {
#pragma unroll
            for (int ss = 0; ss < 16; ss++) ks_acc += Ks[ss][tid];
        }
#pragma unroll
        for (int ss = 0; ss < 16; ss++) {
            float vr[4], kr[4];
#pragma unroll
            for (int i = 0; i < 4; i++) vr[i] = Vs[ss][ty * 4 + i];
#pragma unroll
            for (int j = 0; j < 4; j++) kr[j] = Ks[ss][tx * 4 + j];
#pragma unroll
            for (int i = 0; i < 4; i++)
#pragma unroll
                for (int j = 0; j < 4; j++) acc[i][j] += vr[i] * kr[j];
        }
    }

    float* kvbh = kv + (size_t)bh * DHEAD * DHEAD;
#pragma unroll
    for (int i = 0; i < 4; i++)
#pragma unroll
        for (int j = 0; j < 4; j++)
            atomicAdd(&kvbh[(ty * 4 + i) * DHEAD + tx * 4 + j], acc[i][j]);
    if (tid < 64) atomicAdd(&ksum[bh * DHEAD + tid], ks_acc);
}

// ---------------------------------------------------------------------------
// Attention apply: attn[t, h*64+i] = norm * sum_d q[t,h,d] * kv[b,h,i,d]
// Output is tf32-rounded so the final GEMM needs no conversion.
// ---------------------------------------------------------------------------
__global__ void __launch_bounds__(128)
attn_kernel(const float* __restrict__ Q, const float* __restrict__ kv,
            const float* __restrict__ ksum, float* __restrict__ attn) {
    const int h   = blockIdx.y;
    const int row = blockIdx.x * 128 + threadIdx.x;
    const int b   = row / S_LEN;

    __shared__ float kvs[64][64];
    __shared__ float kss[64];

    const float* kvsrc = kv + (size_t)(b * NHEADS + h) * DHEAD * DHEAD;
    for (int i = threadIdx.x; i < (DHEAD * DHEAD) / 4; i += 128)
        ((float4*)kvs)[i] = ((const float4*)kvsrc)[i];
    if (threadIdx.x < 64) kss[threadIdx.x] = ksum[(b * NHEADS + h) * DHEAD + threadIdx.x];
    __syncthreads();

    float q[64];
    const float* qp = Q + (size_t)row * DMODEL + h * DHEAD;
#pragma unroll
    for (int i = 0; i < 16; i++) ((float4*)q)[i] = ((const float4*)qp)[i];

    float nd = 0.0f;
#pragma unroll
    for (int d = 0; d < 64; d++) nd += q[d] * kss[d];
    const float norm = 1.0f / (nd + 1e-6f);

    float* op = attn + (size_t)row * DMODEL + h * DHEAD;
    for (int i0 = 0; i0 < 64; i0 += 4) {
        unsigned out[4];
#pragma unroll
        for (int u = 0; u < 4; u++) {
            float s = 0.0f;
            const float4* kv4 = (const float4*)kvs[i0 + u];
#pragma unroll
            for (int d4 = 0; d4 < 16; d4++) {
                float4 kvv = kv4[d4];
                s += q[4*d4] * kvv.x + q[4*d4+1] * kvv.y
                   + q[4*d4+2] * kvv.z + q[4*d4+3] * kvv.w;
            }
            out[u] = f2tf(s * norm);
        }
        *(uint4*)&op[i0] = make_uint4(out[0], out[1], out[2], out[3]);
    }
}

// ---------------------------------------------------------------------------
// Launch
// ---------------------------------------------------------------------------
extern "C" void kernel_launch(void* const* d_in, const int* in_sizes, int n_in,
                              void* d_out, int out_size) {
    const float* query = (const float*)d_in[0];
    const float* key_  = (const float*)d_in[1];
    const float* value = (const float*)d_in[2];
    const float* Wq = (const float*)d_in[3];
    const float* bq = (const float*)d_in[4];
    const float* Wk = (const float*)d_in[5];
    const float* bk = (const float*)d_in[6];
    const float* Wv = (const float*)d_in[7];
    const float* bv = (const float*)d_in[8];
    const float* Wo = (const float*)d_in[9];
    const float* bo = (const float*)d_in[10];
    float* out = (float*)d_out;

    float *qf, *kf, *vf, *attn, *kv, *ks, *rq, *rk, *rv, *rw;
    cudaGetSymbolAddress((void**)&qf,   g_q);
    cudaGetSymbolAddress((void**)&kf,   g_k);
    cudaGetSymbolAddress((void**)&vf,   g_v);
    cudaGetSymbolAddress((void**)&attn, g_attn);
    cudaGetSymbolAddress((void**)&kv,   g_kv);
    cudaGetSymbolAddress((void**)&ks,   g_ksum);
    cudaGetSymbolAddress((void**)&rq,   g_rq);
    cudaGetSymbolAddress((void**)&rk,   g_rk);
    cudaGetSymbolAddress((void**)&rv,   g_rv);
    cudaGetSymbolAddress((void**)&rw,   g_rw);
    float* rwq = rw;
    float* rwk = rw + (size_t)DMODEL * DMODEL;
    float* rwv = rw + (size_t)2 * DMODEL * DMODEL;
    float* rwo = rw + (size_t)3 * DMODEL * DMODEL;

    static int smem_set = 0;
    if (!smem_set) {
        cudaFuncSetAttribute(gemm_tf32_kernel<1>,
                             cudaFuncAttributeMaxDynamicSharedMemorySize, GEMM_SMEM_BYTES);
        cudaFuncSetAttribute(gemm_tf32_kernel<0>,
                             cudaFuncAttributeMaxDynamicSharedMemorySize, GEMM_SMEM_BYTES);
        smem_set = 1;
    }

    // tf32 pre-rounding passes
    const int N4_IN = (NROWS * DMODEL) / 4;       // 8388608
    const int N4_W  = (DMODEL * DMODEL) / 4;      // 262144
    round_tf32_kernel<<<N4_IN / 256, 256>>>(query, rq, N4_IN);
    round_tf32_kernel<<<N4_IN / 256, 256>>>(key_,  rk, N4_IN);
    round_tf32_kernel<<<N4_IN / 256, 256>>>(value, rv, N4_IN);
    round_tf32_kernel<<<N4_W / 256, 256>>>(Wq, rwq, N4_W);
    round_tf32_kernel<<<N4_W / 256, 256>>>(Wk, rwk, N4_W);
    round_tf32_kernel<<<N4_W / 256, 256>>>(Wv, rwv, N4_W);
    round_tf32_kernel<<<N4_W / 256, 256>>>(Wo, rwo, N4_W);

    // zero accumulators for atomics
    zero_kernel<<<(BATCH * NHEADS * DHEAD * DHEAD + 255) / 256, 256>>>(kv, BATCH * NHEADS * DHEAD * DHEAD);
    zero_kernel<<<(BATCH * NHEADS * DHEAD + 255) / 256, 256>>>(ks, BATCH * NHEADS * DHEAD);

    dim3 gemm_grid(DMODEL / BN, NROWS / BM);  // (8, 256)
    gemm_tf32_kernel<1><<<gemm_grid, 256, GEMM_SMEM_BYTES>>>(rq, rwq, bq, qf);
    gemm_tf32_kernel<1><<<gemm_grid, 256, GEMM_SMEM_BYTES>>>(rk, rwk, bk, kf);
    gemm_tf32_kernel<0><<<gemm_grid, 256, GEMM_SMEM_BYTES>>>(rv, rwv, bv, vf);

    kv_kernel<<<dim3(BATCH * NHEADS, 8), 256>>>(kf, vf, kv, ks);

    attn_kernel<<<dim3(NROWS / 128, NHEADS), 128>>>(qf, kv, ks, attn);

    gemm_tf32_kernel<0><<<gemm_grid, 256, GEMM_SMEM_BYTES>>>(attn, rwo, bo, out);
}

// round 6
// speedup vs baseline: 2.4849x; 1.4907x over previous
#include <cuda_runtime.h>
#include <cuda_fp16.h>
#include <math.h>
#include <stdint.h>

#define S_LEN   8192
#define BATCH   4
#define DMODEL  1024
#define NROWS   (BATCH * S_LEN)   // 32768
#define NHEADS  16
#define DHEAD   64

// Scratch (device globals: allocation-free per harness rules)
__device__ float  g_q[(size_t)NROWS * DMODEL];    // fp32 Q features
__device__ float  g_k[(size_t)NROWS * DMODEL];    // fp32 K features
__device__ float  g_v[(size_t)NROWS * DMODEL];    // fp32 V
__device__ __half g_hq[(size_t)NROWS * DMODEL];   // fp16-rounded inputs
__device__ __half g_hk[(size_t)NROWS * DMODEL];
__device__ __half g_hv[(size_t)NROWS * DMODEL];
__device__ __half g_hattn[(size_t)NROWS * DMODEL];
__device__ __half g_hw[4][DMODEL * DMODEL];       // fp16-rounded weights
__device__ float  g_kv[BATCH * NHEADS * DHEAD * DHEAD];   // [b,h,dv,dk]
__device__ float  g_ksum[BATCH * NHEADS * DHEAD];

// ---------------------------------------------------------------------------
// helpers
// ---------------------------------------------------------------------------
__device__ __forceinline__ void mma_fp16(float* c, const unsigned* a, const unsigned* b) {
    asm volatile(
        "mma.sync.aligned.m16n8k16.row.col.f32.f16.f16.f32 "
        "{%0,%1,%2,%3}, {%4,%5,%6,%7}, {%8,%9}, {%0,%1,%2,%3};"
        : "+f"(c[0]), "+f"(c[1]), "+f"(c[2]), "+f"(c[3])
        : "r"(a[0]), "r"(a[1]), "r"(a[2]), "r"(a[3]), "r"(b[0]), "r"(b[1]));
}

__device__ __forceinline__ void cp_async16(unsigned smem_addr, const void* gptr) {
    asm volatile("cp.async.cg.shared.global [%0], [%1], 16;"
                 :: "r"(smem_addr), "l"(gptr));
}
__device__ __forceinline__ void cp_commit() {
    asm volatile("cp.async.commit_group;");
}
template <int N>
__device__ __forceinline__ void cp_wait() {
    asm volatile("cp.async.wait_group %0;" :: "n"(N));
}

// ---------------------------------------------------------------------------
// Elementwise fp16 rounding pass (float4 -> 4 halves)
// ---------------------------------------------------------------------------
__global__ void round_fp16_kernel(const float* __restrict__ in,
                                  __half* __restrict__ out, int n4) {
    int i = blockIdx.x * blockDim.x + threadIdx.x;
    if (i < n4) {
        float4 v = ((const float4*)in)[i];
        __half2 h01 = __floats2half2_rn(v.x, v.y);
        __half2 h23 = __floats2half2_rn(v.z, v.w);
        __half2* o = (__half2*)(out + (size_t)i * 4);
        o[0] = h01; o[1] = h23;
    }
}

__global__ void zero_kernel(float* p, int n) {
    int i = blockIdx.x * blockDim.x + threadIdx.x;
    if (i < n) p[i] = 0.0f;
}

// ---------------------------------------------------------------------------
// fp16 GEMM: C[M,1024] = A[M,1024] @ W[1024,1024]^T + bias, optional elu+1.
// A, W pre-rounded to fp16. cp.async double-buffered pipeline.
// k-reassignment: thread tg carries physical k = {4tg..4tg+3} for BOTH
// operands -> each fragment load is one LDS.64.
// Row pad 48 halves (24 words): phase banks 24g+2tg tile all 32 banks.
// BM=128, BN=128, BK=32 halves (2 x k16), 256 threads, warp tile 64x32.
// ---------------------------------------------------------------------------
#define BM 128
#define BN 128
#define BKH 32                    // k halves per chunk
#define SPADH 48                  // halves per smem row (96B)
#define TILEH (BM * SPADH)        // 6144 halves = 12288 B

template <int EPI>
__global__ void __launch_bounds__(256, 2)
gemm_fp16_kernel(const __half* __restrict__ A, const __half* __restrict__ W,
                 const float* __restrict__ bias, float* __restrict__ C) {
    __shared__ __half sh[4 * TILEH];          // [A0,A1,B0,B1] = 48 KB
    __half* Asm = sh;
    __half* Bsm = sh + 2 * TILEH;

    const int tid  = threadIdx.x;
    const int lane = tid & 31;
    const int warp = tid >> 5;
    const int wm   = (warp & 1) * 64;
    const int wn   = (warp >> 1) * 32;
    const int m0   = blockIdx.y * BM;
    const int n0   = blockIdx.x * BN;
    const int g    = lane >> 2;
    const int tg   = lane & 3;

    // global-load mapping: 2 units of 16B per operand per chunk per thread
    // unit u: r = u>>2 (0..127), kc = u&3 (16B = 8 halves each)
    unsigned sbase = (unsigned)__cvta_generic_to_shared(sh);

    float acc[4][4][4];
#pragma unroll
    for (int mt = 0; mt < 4; mt++)
#pragma unroll
        for (int nt = 0; nt < 4; nt++)
#pragma unroll
            for (int i = 0; i < 4; i++) acc[mt][nt][i] = 0.0f;

    const int r0  = tid >> 2;          // unit0 row, unit1 row = r0 + 64
    const int kc  = (tid & 3) * 8;     // half offset within chunk
    const __half* Ap = A + (size_t)(m0 + r0) * DMODEL + kc;
    const __half* Wp = W + (size_t)(n0 + r0) * DMODEL + kc;
    const unsigned a_d0 = sbase + (r0 * SPADH + kc) * 2;
    const unsigned a_d1 = sbase + ((r0 + 64) * SPADH + kc) * 2;
    const unsigned b_d0 = a_d0 + 2 * TILEH * 2;
    const unsigned b_d1 = a_d1 + 2 * TILEH * 2;

    // prologue: chunk 0 into buffer 0
    cp_async16(a_d0, Ap);
    cp_async16(a_d1, Ap + (size_t)64 * DMODEL);
    cp_async16(b_d0, Wp);
    cp_async16(b_d1, Wp + (size_t)64 * DMODEL);
    cp_commit();

    const int NK = DMODEL / BKH;   // 32 chunks
    for (int kt = 0; kt < NK; kt++) {
        const int buf = kt & 1;
        const unsigned nb = ((kt + 1) & 1) * TILEH * 2;
        if (kt + 1 < NK) {
            const __half* Apn = Ap + (kt + 1) * BKH;
            const __half* Wpn = Wp + (kt + 1) * BKH;
            cp_async16(a_d0 + nb, Apn);
            cp_async16(a_d1 + nb, Apn + (size_t)64 * DMODEL);
            cp_async16(b_d0 + nb, Wpn);
            cp_async16(b_d1 + nb, Wpn + (size_t)64 * DMODEL);
            cp_commit();
            cp_wait<1>();
        } else {
            cp_wait<0>();
        }
        __syncthreads();

        const __half* Ab = Asm + buf * TILEH;
        const __half* Bb = Bsm + buf * TILEH;
#pragma unroll
        for (int ks = 0; ks < 2; ks++) {
            const int kk = ks * 16 + 4 * tg;   // physical k base for this thread
            unsigned a[4][4], b[4][2];
#pragma unroll
            for (int mt = 0; mt < 4; mt++) {
                int base = (wm + mt * 16 + g) * SPADH + kk;
                uint2 lo = *(const uint2*)&Ab[base];            // row g
                uint2 hi = *(const uint2*)&Ab[base + 8 * SPADH]; // row g+8
                a[mt][0] = lo.x; a[mt][1] = hi.x; a[mt][2] = lo.y; a[mt][3] = hi.y;
            }
#pragma unroll
            for (int nt = 0; nt < 4; nt++) {
                uint2 bb = *(const uint2*)&Bb[(wn + nt * 8 + g) * SPADH + kk];
                b[nt][0] = bb.x; b[nt][1] = bb.y;
            }
#pragma unroll
            for (int mt = 0; mt < 4; mt++)
#pragma unroll
                for (int nt = 0; nt < 4; nt++)
                    mma_fp16(acc[mt][nt], a[mt], b[nt]);
        }
        __syncthreads();
    }

    // epilogue: bias + optional elu(x)+1, float2 stores
#pragma unroll
    for (int mt = 0; mt < 4; mt++) {
#pragma unroll
        for (int nt = 0; nt < 4; nt++) {
            int row = m0 + wm + mt * 16 + g;
            int col = n0 + wn + nt * 8 + 2 * tg;
            float bv0 = bias[col];
            float bv1 = bias[col + 1];
            float v00 = acc[mt][nt][0] + bv0;
            float v01 = acc[mt][nt][1] + bv1;
            float v10 = acc[mt][nt][2] + bv0;
            float v11 = acc[mt][nt][3] + bv1;
            if (EPI) {
                v00 = (v00 > 0.0f) ? v00 + 1.0f : expf(v00);
                v01 = (v01 > 0.0f) ? v01 + 1.0f : expf(v01);
                v10 = (v10 > 0.0f) ? v10 + 1.0f : expf(v10);
                v11 = (v11 > 0.0f) ? v11 + 1.0f : expf(v11);
            }
            *(float2*)&C[(size_t)row * DMODEL + col]       = make_float2(v00, v01);
            *(float2*)&C[(size_t)(row + 8) * DMODEL + col] = make_float2(v10, v11);
        }
    }
}

// ---------------------------------------------------------------------------
// KV chain: kv[b,h,i,j] = sum_s V[b,s,h,i] * K[b,s,h,j];  ksum[b,h,j] = sum_s K
// ---------------------------------------------------------------------------
__global__ void __launch_bounds__(256)
kv_kernel(const float* __restrict__ K, const float* __restrict__ V,
          float* __restrict__ kv, float* __restrict__ ksum) {
    const int bh = blockIdx.x;
    const int b  = bh / NHEADS;
    const int h  = bh % NHEADS;
    const int tid = threadIdx.x;
    const int ty  = tid >> 4;
    const int tx  = tid & 15;

    __shared__ float Ks[16][64];
    __shared__ float Vs[16][64];

    float acc[4][4];
#pragma unroll
    for (int i = 0; i < 4; i++)
#pragma unroll
        for (int j = 0; j < 4; j++) acc[i][j] = 0.0f;
    float ks_acc = 0.0f;

    const float* Kbase = K + (size_t)b * S_LEN * DMODEL + h * DHEAD;
    const float* Vbase = V + (size_t)b * S_LEN * DMODEL + h * DHEAD;
    const int s0 = blockIdx.y * (S_LEN / 8);

    for (int s = s0; s < s0 + (S_LEN / 8); s += 16) {
        __syncthreads();
        {
            int r  = tid >> 4;
            int c4 = (tid & 15) << 2;
            *(float4*)&Ks[r][c4] = *(const float4*)&Kbase[(size_t)(s + r) * DMODEL + c4];
            *(float4*)&Vs[r][c4] = *(const float4*)&Vbase[(size_t)(s + r) * DMODEL + c4];
        }
        __syncthreads();
        if (tid < 64) {
#pragma unroll
            for (int ss = 0; ss < 16; ss++) ks_acc += Ks[ss][tid];
        }
#pragma unroll
        for (int ss = 0; ss < 16; ss++) {
            float vr[4], kr[4];
#pragma unroll
            for (int i = 0; i < 4; i++) vr[i] = Vs[ss][ty * 4 + i];
#pragma unroll
            for (int j = 0; j < 4; j++) kr[j] = Ks[ss][tx * 4 + j];
#pragma unroll
            for (int i = 0; i < 4; i++)
#pragma unroll
                for (int j = 0; j < 4; j++) acc[i][j] += vr[i] * kr[j];
        }
    }

    float* kvbh = kv + (size_t)bh * DHEAD * DHEAD;
#pragma unroll
    for (int i = 0; i < 4; i++)
#pragma unroll
        for (int j = 0; j < 4; j++)
            atomicAdd(&kvbh[(ty * 4 + i) * DHEAD + tx * 4 + j], acc[i][j]);
    if (tid < 64) atomicAdd(&ksum[bh * DHEAD + tid], ks_acc);
}

// ---------------------------------------------------------------------------
// Attention apply; output rounded to fp16 for the final GEMM
// ---------------------------------------------------------------------------
__global__ void __launch_bounds__(128)
attn_kernel(const float* __restrict__ Q, const float* __restrict__ kv,
            const float* __restrict__ ksum, __half* __restrict__ attn) {
    const int h   = blockIdx.y;
    const int row = blockIdx.x * 128 + threadIdx.x;
    const int b   = row / S_LEN;

    __shared__ float kvs[64][64];
    __shared__ float kss[64];

    const float* kvsrc = kv + (size_t)(b * NHEADS + h) * DHEAD * DHEAD;
    for (int i = threadIdx.x; i < (DHEAD * DHEAD) / 4; i += 128)
        ((float4*)kvs)[i] = ((const float4*)kvsrc)[i];
    if (threadIdx.x < 64) kss[threadIdx.x] = ksum[(b * NHEADS + h) * DHEAD + threadIdx.x];
    __syncthreads();

    float q[64];
    const float* qp = Q + (size_t)row * DMODEL + h * DHEAD;
#pragma unroll
    for (int i = 0; i < 16; i++) ((float4*)q)[i] = ((const float4*)qp)[i];

    float nd = 0.0f;
#pragma unroll
    for (int d = 0; d < 64; d++) nd += q[d] * kss[d];
    const float norm = 1.0f / (nd + 1e-6f);

    __half* op = attn + (size_t)row * DMODEL + h * DHEAD;
    for (int i0 = 0; i0 < 64; i0 += 4) {
        float out[4];
#pragma unroll
        for (int u = 0; u < 4; u++) {
            float s = 0.0f;
            const float4* kv4 = (const float4*)kvs[i0 + u];
#pragma unroll
            for (int d4 = 0; d4 < 16; d4++) {
                float4 kvv = kv4[d4];
                s += q[4*d4] * kvv.x + q[4*d4+1] * kvv.y
                   + q[4*d4+2] * kvv.z + q[4*d4+3] * kvv.w;
            }
            out[u] = s * norm;
        }
        __half2 h01 = __floats2half2_rn(out[0], out[1]);
        __half2 h23 = __floats2half2_rn(out[2], out[3]);
        *(__half2*)&op[i0]     = h01;
        *(__half2*)&op[i0 + 2] = h23;
    }
}

// ---------------------------------------------------------------------------
// Launch
// ---------------------------------------------------------------------------
extern "C" void kernel_launch(void* const* d_in, const int* in_sizes, int n_in,
                              void* d_out, int out_size) {
    const float* query = (const float*)d_in[0];
    const float* key_  = (const float*)d_in[1];
    const float* value = (const float*)d_in[2];
    const float* Wq = (const float*)d_in[3];
    const float* bq = (const float*)d_in[4];
    const float* Wk = (const float*)d_in[5];
    const float* bk = (const float*)d_in[6];
    const float* Wv = (const float*)d_in[7];
    const float* bv = (const float*)d_in[8];
    const float* Wo = (const float*)d_in[9];
    const float* bo = (const float*)d_in[10];
    float* out = (float*)d_out;

    float *qf, *kf, *vf, *kv, *ks;
    __half *hq, *hk, *hv, *hattn, *hw;
    cudaGetSymbolAddress((void**)&qf,    g_q);
    cudaGetSymbolAddress((void**)&kf,    g_k);
    cudaGetSymbolAddress((void**)&vf,    g_v);
    cudaGetSymbolAddress((void**)&kv,    g_kv);
    cudaGetSymbolAddress((void**)&ks,    g_ksum);
    cudaGetSymbolAddress((void**)&hq,    g_hq);
    cudaGetSymbolAddress((void**)&hk,    g_hk);
    cudaGetSymbolAddress((void**)&hv,    g_hv);
    cudaGetSymbolAddress((void**)&hattn, g_hattn);
    cudaGetSymbolAddress((void**)&hw,    g_hw);
    __half* hwq = hw;
    __half* hwk = hw + (size_t)DMODEL * DMODEL;
    __half* hwv = hw + (size_t)2 * DMODEL * DMODEL;
    __half* hwo = hw + (size_t)3 * DMODEL * DMODEL;

    // fp16 pre-rounding passes
    const int N4_IN = (NROWS * DMODEL) / 4;
    const int N4_W  = (DMODEL * DMODEL) / 4;
    round_fp16_kernel<<<N4_IN / 256, 256>>>(query, hq, N4_IN);
    round_fp16_kernel<<<N4_IN / 256, 256>>>(key_,  hk, N4_IN);
    round_fp16_kernel<<<N4_IN / 256, 256>>>(value, hv, N4_IN);
    round_fp16_kernel<<<N4_W / 256, 256>>>(Wq, hwq, N4_W);
    round_fp16_kernel<<<N4_W / 256, 256>>>(Wk, hwk, N4_W);
    round_fp16_kernel<<<N4_W / 256, 256>>>(Wv, hwv, N4_W);
    round_fp16_kernel<<<N4_W / 256, 256>>>(Wo, hwo, N4_W);

    // zero accumulators for atomics
    zero_kernel<<<(BATCH * NHEADS * DHEAD * DHEAD + 255) / 256, 256>>>(kv, BATCH * NHEADS * DHEAD * DHEAD);
    zero_kernel<<<(BATCH * NHEADS * DHEAD + 255) / 256, 256>>>(ks, BATCH * NHEADS * DHEAD);

    dim3 gemm_grid(DMODEL / BN, NROWS / BM);  // (8, 256)
    gemm_fp16_kernel<1><<<gemm_grid, 256>>>(hq, hwq, bq, qf);
    gemm_fp16_kernel<1><<<gemm_grid, 256>>>(hk, hwk, bk, kf);
    gemm_fp16_kernel<0><<<gemm_grid, 256>>>(hv, hwv, bv, vf);

    kv_kernel<<<dim3(BATCH * NHEADS, 8), 256>>>(kf, vf, kv, ks);

    attn_kernel<<<dim3(NROWS / 128, NHEADS), 128>>>(qf, kv, ks, hattn);

    gemm_fp16_kernel<0><<<gemm_grid, 256>>>(hattn, hwo, bo, out);
}